// round 10
// baseline (speedup 1.0000x reference)
#include <cuda_runtime.h>
#include <cuda_fp16.h>
#include <math.h>

#define T_SEQ 2048
#define NH 16
#define HD 64
#define C_EMB 1024
#define MTOT 4096  /* B*T */

// Scratch (allocation-free rule: __device__ globals)
__device__ float g_qkv[MTOT * 3 * C_EMB];   // 48 MB (tf32-rounded by GEMM1 epilogue)
__device__ float g_attn[MTOT * C_EMB];      // 16 MB (tf32-rounded by attn epilogue)
__device__ float g_xc[MTOT * C_EMB];        // 16 MB tf32-rounded x
__device__ float g_wac[C_EMB * 3 * C_EMB];  // 12 MB tf32-rounded w_attn
__device__ float g_wpc[C_EMB * C_EMB];      //  4 MB tf32-rounded w_proj
__device__ __half g_vth[2 * NH * HD * T_SEQ]; // 8 MB V^T in half: [b][h][d][t]
__device__ float g_mask[NH * T_SEQ];
__device__ int   g_cutoff[NH];

__device__ __forceinline__ float sigmoidf_(float x) { return 1.f / (1.f + expf(-x)); }

__device__ __forceinline__ unsigned f2tf32(float x) {
    unsigned r;
    asm("cvt.rna.tf32.f32 %0, %1;" : "=r"(r) : "f"(x));
    return r;
}

__device__ __forceinline__ void cp16(void* smem, const void* g) {
    unsigned s = (unsigned)__cvta_generic_to_shared(smem);
    asm volatile("cp.async.cg.shared.global [%0], [%1], 16;" :: "r"(s), "l"(g));
}
__device__ __forceinline__ void cp_commit() { asm volatile("cp.async.commit_group;"); }
__device__ __forceinline__ void cp_wait0()  { asm volatile("cp.async.wait_group 0;"); }
__device__ __forceinline__ void cp_wait1()  { asm volatile("cp.async.wait_group 1;"); }

__device__ __forceinline__ void mma_tf32(float c[4], unsigned a0, unsigned a1,
                                         unsigned a2, unsigned a3,
                                         unsigned b0, unsigned b1) {
    asm volatile(
        "mma.sync.aligned.m16n8k8.row.col.f32.tf32.tf32.f32 "
        "{%0,%1,%2,%3}, {%4,%5,%6,%7}, {%8,%9}, {%0,%1,%2,%3};"
        : "+f"(c[0]), "+f"(c[1]), "+f"(c[2]), "+f"(c[3])
        : "r"(a0), "r"(a1), "r"(a2), "r"(a3), "r"(b0), "r"(b1));
}

__device__ __forceinline__ void mma_f16(float c[4], unsigned a0, unsigned a1,
                                        unsigned a2, unsigned a3,
                                        unsigned b0, unsigned b1) {
    asm volatile(
        "mma.sync.aligned.m16n8k16.row.col.f32.f16.f16.f32 "
        "{%0,%1,%2,%3}, {%4,%5,%6,%7}, {%8,%9}, {%0,%1,%2,%3};"
        : "+f"(c[0]), "+f"(c[1]), "+f"(c[2]), "+f"(c[3])
        : "r"(a0), "r"(a1), "r"(a2), "r"(a3), "r"(b0), "r"(b1));
}

__device__ __forceinline__ unsigned packh2(float lo, float hi) {
    __half2 h = __floats2half2_rn(lo, hi);
    return *(unsigned*)&h;
}

// ---------------------------------------------------------------------------
// Elementwise tf32 rounding (rna), float4-vectorized. n4 = n/4.
// ---------------------------------------------------------------------------
__global__ void cvt_tf32_k(const float4* __restrict__ s, float4* __restrict__ d, int n4)
{
    int i = blockIdx.x * blockDim.x + threadIdx.x;
    if (i >= n4) return;
    float4 v = s[i];
    v.x = __uint_as_float(f2tf32(v.x));
    v.y = __uint_as_float(f2tf32(v.y));
    v.z = __uint_as_float(f2tf32(v.z));
    v.w = __uint_as_float(f2tf32(v.w));
    d[i] = v;
}

// ---------------------------------------------------------------------------
// V -> V^T half: g_vth[(b*NH+h)*HD + d][t] = half(qkv[b][t][2048 + h*64 + d])
// ---------------------------------------------------------------------------
__global__ void vt_convert(const float* __restrict__ qkv, __half* __restrict__ vt)
{
    __shared__ float tile[32][33];
    int bh = blockIdx.z;                 // b*NH + h
    int d0 = blockIdx.y << 5;            // 0 / 32
    int t0 = blockIdx.x << 5;
    int b = bh >> 4, h = bh & 15;
    int tx = threadIdx.x, ty = threadIdx.y;
#pragma unroll
    for (int i = ty; i < 32; i += 8)
        tile[i][tx] = qkv[((size_t)(b * T_SEQ + t0 + i)) * 3072 + 2048 + (h << 6) + d0 + tx];
    __syncthreads();
#pragma unroll
    for (int i = ty; i < 32; i += 8)
        vt[((size_t)bh * HD + d0 + i) * T_SEQ + t0 + tx] = __float2half(tile[tx][i]);
}

// ---------------------------------------------------------------------------
// Prep: per-head span/period/ratio, 1-D mask table over rel, span_loss scalar.
// ---------------------------------------------------------------------------
__global__ void prep_kernel(const float* __restrict__ span_p,
                            const float* __restrict__ period_w,
                            const float* __restrict__ ratio_w,
                            float* loss_out)
{
    __shared__ float s_span[NH], s_period[NH], s_ratio[NH];
    int tid = threadIdx.x;
    if (tid < NH) {
        float span   = 2048.f * sigmoidf_(span_p[tid]);
        float period = 2.f + 2.f * sigmoidf_(period_w[tid]);
        float ratio  = -0.25f + 0.5f * sigmoidf_(ratio_w[tid]);
        s_span[tid] = span; s_period[tid] = period; s_ratio[tid] = ratio;
        int cut = (int)floorf(32.f + span) + 1;
        if (cut > T_SEQ) cut = T_SEQ;
        g_cutoff[tid] = cut;
    }
    __syncthreads();
    for (int idx = tid; idx < NH * T_SEQ; idx += blockDim.x) {
        int hh = idx >> 11, rel = idx & (T_SEQ - 1);
        float span = s_span[hh], period = s_period[hh], ratio = s_ratio[hh];
        float mp = (32.f - (float)rel + span) * (1.f / 32.f);
        mp = fminf(fmaxf(mp, 0.f), 1.f);
        float amp = period * 0.25f;
        float wave = 0.5f * (cosf(6.28318530717958647692f * (float)rel / period) + 1.f) * amp
                     + 0.5f + period * ratio;
        wave = fminf(fmaxf(wave, 0.f), 1.f);
        g_mask[idx] = mp * wave;
    }
    if (tid == 0 && loss_out) {
        float s = 0.f;
        for (int h = 0; h < NH; h++) {
            float lt = 1.f / s_period[h] + 2.f * s_ratio[h] - 0.25f + 0.5f;
            s += (s_span[h] + 32.f) * lt;
        }
        *loss_out = 2e-6f * s * (1.f / 16.f);
    }
}

// ---------------------------------------------------------------------------
// TF32 tensor-core GEMM: C[M,N] = A[M,K] @ B[K,N] + bias[N]
// Inputs pre-rounded to tf32. CTA 128x256, 8 warps (2x4), warp 64x64, BK=16,
// 3-stage cp.async pipeline, dynamic smem. M%128==0, N%256==0, K%16==0, K>=32.
// ---------------------------------------------------------------------------
#define GA_STAGE (128 * 20)
#define GB_STAGE (16 * 264)
#define GEMM_SMEM (3 * (GA_STAGE + GB_STAGE) * 4)

template<bool ROUND>
__global__ __launch_bounds__(256, 1)
void gemm_tf32(const float* __restrict__ A, const float* __restrict__ B,
               const float* __restrict__ bias, float* __restrict__ C,
               int M, int N, int K)
{
    extern __shared__ float sg[];
    float* Asm = sg;                    // [3][128][20]
    float* Bsm = sg + 3 * GA_STAGE;     // [3][16][264]

    int tid  = threadIdx.x;
    int wid  = tid >> 5, lane = tid & 31;
    int gro  = lane >> 2, tig = lane & 3;
    int wm   = (wid >> 2) << 6;   // 0/64
    int wn   = (wid & 3) << 6;    // 0/64/128/192
    int bm   = blockIdx.y << 7;
    int bn   = blockIdx.x << 8;

    float acc[4][8][4];
#pragma unroll
    for (int mt = 0; mt < 4; mt++)
#pragma unroll
        for (int nt = 0; nt < 8; nt++)
#pragma unroll
            for (int e = 0; e < 4; e++) acc[mt][nt][e] = 0.f;

    int nk = K >> 4;

    auto load_stage = [&](int s, int kt) {
        int kg = kt << 4;
        float* as = Asm + s * GA_STAGE;
        float* bs = Bsm + s * GB_STAGE;
#pragma unroll
        for (int it = 0; it < 2; it++) {
            int id = tid + (it << 8);
            int r = id >> 2, kc = (id & 3) << 2;
            cp16(&as[r * 20 + kc], A + (size_t)(bm + r) * K + kg + kc);
        }
#pragma unroll
        for (int it = 0; it < 4; it++) {
            int id = tid + (it << 8);
            int br = id >> 6, nc = (id & 63) << 2;
            cp16(&bs[br * 264 + nc], B + (size_t)(kg + br) * N + bn + nc);
        }
        cp_commit();
    };

    load_stage(0, 0);
    load_stage(1, 1);

    int sc = 0, sl = 2;
    for (int k0 = 0; k0 < nk; k0++) {
        cp_wait1();
        __syncthreads();
        if (k0 + 2 < nk) load_stage(sl, k0 + 2);
        else cp_commit();   // keep group count in lockstep for wait_group 1

        const float* as = Asm + sc * GA_STAGE;
        const float* bs = Bsm + sc * GB_STAGE;
#pragma unroll
        for (int ks = 0; ks < 2; ks++) {
            unsigned af[4][4];
#pragma unroll
            for (int mt = 0; mt < 4; mt++) {
                int rb = wm + (mt << 4) + gro;
                int kc = (ks << 3) + tig;
                af[mt][0] = __float_as_uint(as[rb * 20 + kc]);
                af[mt][1] = __float_as_uint(as[(rb + 8) * 20 + kc]);
                af[mt][2] = __float_as_uint(as[rb * 20 + kc + 4]);
                af[mt][3] = __float_as_uint(as[(rb + 8) * 20 + kc + 4]);
            }
            unsigned bf[8][2];
#pragma unroll
            for (int nt = 0; nt < 8; nt++) {
                int nb = wn + (nt << 3) + gro;
                int kr = (ks << 3) + tig;
                bf[nt][0] = __float_as_uint(bs[kr * 264 + nb]);
                bf[nt][1] = __float_as_uint(bs[(kr + 4) * 264 + nb]);
            }
#pragma unroll
            for (int mt = 0; mt < 4; mt++)
#pragma unroll
                for (int nt = 0; nt < 8; nt++)
                    mma_tf32(acc[mt][nt], af[mt][0], af[mt][1], af[mt][2], af[mt][3],
                             bf[nt][0], bf[nt][1]);
        }
        sc = (sc == 2) ? 0 : sc + 1;
        sl = (sl == 2) ? 0 : sl + 1;
    }

#pragma unroll
    for (int mt = 0; mt < 4; mt++) {
        int row = bm + wm + (mt << 4) + gro;
#pragma unroll
        for (int nt = 0; nt < 8; nt++) {
            int col = bn + wn + (nt << 3) + (tig << 1);
            float2 bz = *(const float2*)(bias + col);
            float2 o0, o1;
            o0.x = acc[mt][nt][0] + bz.x; o0.y = acc[mt][nt][1] + bz.y;
            o1.x = acc[mt][nt][2] + bz.x; o1.y = acc[mt][nt][3] + bz.y;
            if (ROUND) {
                o0.x = __uint_as_float(f2tf32(o0.x));
                o0.y = __uint_as_float(f2tf32(o0.y));
                o1.x = __uint_as_float(f2tf32(o1.x));
                o1.y = __uint_as_float(f2tf32(o1.y));
            }
            *(float2*)(C + (size_t)row * N + col)       = o0;
            *(float2*)(C + (size_t)(row + 8) * N + col) = o1;
        }
    }
}

// ---------------------------------------------------------------------------
// Banded flash attention: tf32 QK^T + fp32 softmax + fp16 PV (m16n8k16).
// CTA = (b, h, 128 query rows), 8 warps. K staged tf32, V staged as V^T half.
// P: S C-layout packs directly into fp16 A-frags (no shuffle transpose).
// ---------------------------------------------------------------------------
#define KPAD 68
#define VTPAD 72
#define KS_ELE (64 * KPAD)          /* floats  */
#define VT_ELE (64 * VTPAD)         /* halves  */
#define ATTN_SMEM (2 * KS_ELE * 4 + 2 * VT_ELE * 2)

__global__ __launch_bounds__(256)
void attn_tc(const float* __restrict__ qkv, const __half* __restrict__ vth,
             float* __restrict__ yout)
{
    extern __shared__ char smc[];
    float* Kb0 = (float*)smc;
    float* Kb1 = Kb0 + KS_ELE;
    __half* V0 = (__half*)(smc + 2 * KS_ELE * 4);
    __half* V1 = V0 + VT_ELE;

    int tid  = threadIdx.x;
    int wid  = tid >> 5, lane = tid & 31;
    int gro  = lane >> 2, tig = lane & 3;
    int i0   = blockIdx.x << 7;
    int h    = blockIdx.y, b = blockIdx.z;
    int baseq = h << 6;
    int wrow = wid << 4;
    int ir0 = i0 + wrow + gro;
    int ir1 = ir0 + 8;

    // staging decomposition
    int krow = tid >> 4, kcol = (tid & 15) << 2;   // K: 4 iters of 256
    int vrow = tid >> 3, vcol = (tid & 7) << 3;    // VT: 2 iters of 256 (half idx)

    // ---- Q fragments (raw tf32 bits, once per block) ----
    const float* qp = qkv + ((size_t)(b * T_SEQ + i0 + wrow)) * 3072 + baseq;
    unsigned qf[8][4];
#pragma unroll
    for (int kt = 0; kt < 8; kt++) {
        int kc = (kt << 3) + tig;
        qf[kt][0] = __float_as_uint(qp[gro * 3072 + kc]);
        qf[kt][1] = __float_as_uint(qp[(gro + 8) * 3072 + kc]);
        qf[kt][2] = __float_as_uint(qp[gro * 3072 + kc + 4]);
        qf[kt][3] = __float_as_uint(qp[(gro + 8) * 3072 + kc + 4]);
    }

    float m0 = -1e30f, m1 = -1e30f, l0 = 0.f, l1 = 0.f;
    float oreg[8][4];
#pragma unroll
    for (int nt = 0; nt < 8; nt++)
#pragma unroll
        for (int e = 0; e < 4; e++) oreg[nt][e] = 0.f;

    int cutoff = g_cutoff[h];
    int t0 = i0 - cutoff + 1;
    int jstart = (t0 <= 0) ? 0 : (t0 & ~63);
    int jend = i0 + 64;                       // last tile for rows i0..i0+127
    const float* maskh = g_mask + h * T_SEQ;
    const __half* vbase = vth + ((size_t)(b * NH + h)) * HD * T_SEQ;

    // prefetch first tile into stage 0
    {
        const float* kb = qkv + ((size_t)(b * T_SEQ + jstart)) * 3072 + baseq + 1024;
#pragma unroll
        for (int it = 0; it < 4; it++) {
            int id = tid + (it << 8);
            int row = id >> 4, col = (id & 15) << 2;
            cp16(&Kb0[row * KPAD + col], kb + (size_t)row * 3072 + col);
        }
#pragma unroll
        for (int it = 0; it < 2; it++) {
            int id = tid + (it << 8);
            int row = id >> 3, col = (id & 7) << 3;
            cp16(&V0[row * VTPAD + col], vbase + (size_t)row * T_SEQ + jstart + col);
        }
        cp_commit();
    }

    int buf = 0;
    for (int j0 = jstart; j0 <= jend; j0 += 64) {
        cp_wait0();
        __syncthreads();
        if (j0 + 64 <= jend) {
            float*  Kn = buf ? Kb0 : Kb1;
            __half* Vn = buf ? V0  : V1;
            const float* kb = qkv + ((size_t)(b * T_SEQ + j0 + 64)) * 3072 + baseq + 1024;
#pragma unroll
            for (int it = 0; it < 4; it++) {
                int id = tid + (it << 8);
                int row = id >> 4, col = (id & 15) << 2;
                cp16(&Kn[row * KPAD + col], kb + (size_t)row * 3072 + col);
            }
#pragma unroll
            for (int it = 0; it < 2; it++) {
                int id = tid + (it << 8);
                int row = id >> 3, col = (id & 7) << 3;
                cp16(&Vn[row * VTPAD + col], vbase + (size_t)row * T_SEQ + j0 + 64 + col);
            }
            cp_commit();
        }
        const float*  Kc = buf ? Kb1 : Kb0;
        const __half* Vc = buf ? V1  : V0;

        // ---- S = Q K^T (16x64 per warp, tf32) ----
        float sreg[8][4];
#pragma unroll
        for (int nt = 0; nt < 8; nt++) {
#pragma unroll
            for (int e = 0; e < 4; e++) sreg[nt][e] = 0.f;
            int jb = (nt << 3) + gro;
#pragma unroll
            for (int kt = 0; kt < 8; kt++) {
                unsigned b0 = __float_as_uint(Kc[jb * KPAD + (kt << 3) + tig]);
                unsigned b1 = __float_as_uint(Kc[jb * KPAD + (kt << 3) + tig + 4]);
                mma_tf32(sreg[nt], qf[kt][0], qf[kt][1], qf[kt][2], qf[kt][3], b0, b1);
            }
        }

        // ---- online softmax ----
        float vm0 = -1e30f, vm1 = -1e30f;
#pragma unroll
        for (int nt = 0; nt < 8; nt++) {
            int jn = j0 + (nt << 3) + (tig << 1);
            float s0 = (jn     <= ir0) ? sreg[nt][0] * 0.125f : -1e30f;
            float s1 = (jn + 1 <= ir0) ? sreg[nt][1] * 0.125f : -1e30f;
            float s2 = (jn     <= ir1) ? sreg[nt][2] * 0.125f : -1e30f;
            float s3 = (jn + 1 <= ir1) ? sreg[nt][3] * 0.125f : -1e30f;
            sreg[nt][0] = s0; sreg[nt][1] = s1; sreg[nt][2] = s2; sreg[nt][3] = s3;
            vm0 = fmaxf(vm0, fmaxf(s0, s1));
            vm1 = fmaxf(vm1, fmaxf(s2, s3));
        }
        vm0 = fmaxf(vm0, __shfl_xor_sync(0xffffffffu, vm0, 1));
        vm0 = fmaxf(vm0, __shfl_xor_sync(0xffffffffu, vm0, 2));
        vm1 = fmaxf(vm1, __shfl_xor_sync(0xffffffffu, vm1, 1));
        vm1 = fmaxf(vm1, __shfl_xor_sync(0xffffffffu, vm1, 2));
        float mn0 = fmaxf(m0, vm0), mn1 = fmaxf(m1, vm1);
        float f0 = __expf(m0 - mn0), f1 = __expf(m1 - mn1);
        float rs0 = 0.f, rs1 = 0.f;
#pragma unroll
        for (int nt = 0; nt < 8; nt++) {
            int jn = j0 + (nt << 3) + (tig << 1);
            float p0 = 0.f, p1 = 0.f, p2 = 0.f, p3 = 0.f;
            if (jn <= ir0) {
                int r = ir0 - jn; if (r > 2047) r = 2047;
                p0 = __expf(sreg[nt][0] - mn0) * __ldg(maskh + r);
            }
            if (jn + 1 <= ir0) {
                int r = ir0 - jn - 1; if (r > 2047) r = 2047;
                p1 = __expf(sreg[nt][1] - mn0) * __ldg(maskh + r);
            }
            if (jn <= ir1) {
                int r = ir1 - jn; if (r > 2047) r = 2047;
                p2 = __expf(sreg[nt][2] - mn1) * __ldg(maskh + r);
            }
            if (jn + 1 <= ir1) {
                int r = ir1 - jn - 1; if (r > 2047) r = 2047;
                p3 = __expf(sreg[nt][3] - mn1) * __ldg(maskh + r);
            }
            sreg[nt][0] = p0; sreg[nt][1] = p1; sreg[nt][2] = p2; sreg[nt][3] = p3;
            rs0 += p0 + p1; rs1 += p2 + p3;
        }
        rs0 += __shfl_xor_sync(0xffffffffu, rs0, 1);
        rs0 += __shfl_xor_sync(0xffffffffu, rs0, 2);
        rs1 += __shfl_xor_sync(0xffffffffu, rs1, 1);
        rs1 += __shfl_xor_sync(0xffffffffu, rs1, 2);
        l0 = l0 * f0 + rs0; m0 = mn0;
        l1 = l1 * f1 + rs1; m1 = mn1;
#pragma unroll
        for (int nt = 0; nt < 8; nt++) {
            oreg[nt][0] *= f0; oreg[nt][1] *= f0;
            oreg[nt][2] *= f1; oreg[nt][3] *= f1;
        }

        // ---- O += P V : fp16 m16n8k16, P packed straight from C-layout ----
#pragma unroll
        for (int kt = 0; kt < 4; kt++) {
            unsigned a0 = packh2(sreg[2 * kt][0],     sreg[2 * kt][1]);
            unsigned a1 = packh2(sreg[2 * kt][2],     sreg[2 * kt][3]);
            unsigned a2 = packh2(sreg[2 * kt + 1][0], sreg[2 * kt + 1][1]);
            unsigned a3 = packh2(sreg[2 * kt + 1][2], sreg[2 * kt + 1][3]);
            int kb = (kt << 4) + (tig << 1);
#pragma unroll
            for (int nt = 0; nt < 8; nt++) {
                int nb = (nt << 3) + gro;
                unsigned b0 = *(const unsigned*)&Vc[nb * VTPAD + kb];
                unsigned b1 = *(const unsigned*)&Vc[nb * VTPAD + kb + 8];
                mma_f16(oreg[nt], a0, a1, a2, a3, b0, b1);
            }
        }
        buf ^= 1;
    }

    // ---- epilogue (tf32-rounded: feeds GEMM2) ----
    float inv0 = 1.f / l0, inv1 = 1.f / l1;
#pragma unroll
    for (int nt = 0; nt < 8; nt++) {
        int col = baseq + (nt << 3) + (tig << 1);
        float2 o0, o1;
        o0.x = __uint_as_float(f2tf32(oreg[nt][0] * inv0));
        o0.y = __uint_as_float(f2tf32(oreg[nt][1] * inv0));
        o1.x = __uint_as_float(f2tf32(oreg[nt][2] * inv1));
        o1.y = __uint_as_float(f2tf32(oreg[nt][3] * inv1));
        *(float2*)(yout + ((size_t)(b * T_SEQ + ir0)) * 1024 + col) = o0;
        *(float2*)(yout + ((size_t)(b * T_SEQ + ir1)) * 1024 + col) = o1;
    }
}

// ---------------------------------------------------------------------------
extern "C" void kernel_launch(void* const* d_in, const int* in_sizes, int n_in,
                              void* d_out, int out_size)
{
    const float* x        = (const float*)d_in[0];
    const float* w_attn   = (const float*)d_in[1];
    const float* b_attn   = (const float*)d_in[2];
    const float* w_proj   = (const float*)d_in[3];
    const float* b_proj   = (const float*)d_in[4];
    const float* span_p   = (const float*)d_in[5];
    const float* period_w = (const float*)d_in[6];
    const float* ratio_w  = (const float*)d_in[7];
    float* out = (float*)d_out;

    void* p;
    cudaGetSymbolAddress(&p, g_qkv);  float*  qkv  = (float*)p;
    cudaGetSymbolAddress(&p, g_attn); float*  attn = (float*)p;
    cudaGetSymbolAddress(&p, g_xc);   float*  xc   = (float*)p;
    cudaGetSymbolAddress(&p, g_wac);  float*  wac  = (float*)p;
    cudaGetSymbolAddress(&p, g_wpc);  float*  wpc  = (float*)p;
    cudaGetSymbolAddress(&p, g_vth);  __half* vth  = (__half*)p;

    cudaFuncSetAttribute(gemm_tf32<true>,  cudaFuncAttributeMaxDynamicSharedMemorySize, GEMM_SMEM);
    cudaFuncSetAttribute(gemm_tf32<false>, cudaFuncAttributeMaxDynamicSharedMemorySize, GEMM_SMEM);
    cudaFuncSetAttribute(attn_tc, cudaFuncAttributeMaxDynamicSharedMemorySize, ATTN_SMEM);

    float* loss_ptr = (out_size > MTOT * C_EMB) ? out + MTOT * C_EMB : nullptr;

    prep_kernel<<<1, 256>>>(span_p, period_w, ratio_w, loss_ptr);
    cvt_tf32_k<<<(MTOT * C_EMB / 4) / 256, 256>>>((const float4*)x, (float4*)xc,
                                                  MTOT * C_EMB / 4);
    cvt_tf32_k<<<(C_EMB * 3 * C_EMB / 4) / 256, 256>>>((const float4*)w_attn, (float4*)wac,
                                                       C_EMB * 3 * C_EMB / 4);
    cvt_tf32_k<<<(C_EMB * C_EMB / 4) / 256, 256>>>((const float4*)w_proj, (float4*)wpc,
                                                   C_EMB * C_EMB / 4);
    gemm_tf32<true><<<dim3(3 * C_EMB / 256, MTOT / 128), 256, GEMM_SMEM>>>(
        xc, wac, b_attn, qkv, MTOT, 3 * C_EMB, C_EMB);
    vt_convert<<<dim3(T_SEQ / 32, HD / 32, 2 * NH), dim3(32, 8)>>>(qkv, vth);
    attn_tc<<<dim3(T_SEQ / 128, NH, 2), 256, ATTN_SMEM>>>(qkv, vth, attn);
    gemm_tf32<false><<<dim3(C_EMB / 256, MTOT / 128), 256, GEMM_SMEM>>>(
        attn, wpc, b_proj, out, MTOT, C_EMB, C_EMB);
}

// round 14
// speedup vs baseline: 1.4131x; 1.4131x over previous
#include <cuda_runtime.h>
#include <cuda_fp16.h>
#include <math.h>

#define T_SEQ 2048
#define NH 16
#define HD 64
#define C_EMB 1024
#define MTOT 4096  /* B*T */

// Scratch (allocation-free rule: __device__ globals)
__device__ __half g_qkv[MTOT * 3 * C_EMB];    // 24 MB fp16 qkv
__device__ __half g_attn[MTOT * C_EMB];       //  8 MB fp16 attention out
__device__ __half g_xh[MTOT * C_EMB];         //  8 MB fp16 x
__device__ __half g_wah[3 * C_EMB * C_EMB];   //  6 MB w_attn^T [N=3072][K=1024] fp16
__device__ __half g_wph[C_EMB * C_EMB];       //  2 MB w_proj^T [1024][1024] fp16
__device__ __half g_vth[2 * NH * HD * T_SEQ]; //  8 MB V^T fp16 [b][h][d][t]
__device__ float g_mask[NH * T_SEQ];
__device__ int   g_cutoff[NH];

__device__ __forceinline__ float sigmoidf_(float x) { return 1.f / (1.f + expf(-x)); }

__device__ __forceinline__ void cp16(void* smem, const void* g) {
    unsigned s = (unsigned)__cvta_generic_to_shared(smem);
    asm volatile("cp.async.cg.shared.global [%0], [%1], 16;" :: "r"(s), "l"(g));
}
__device__ __forceinline__ void cp_commit() { asm volatile("cp.async.commit_group;"); }
__device__ __forceinline__ void cp_wait0()  { asm volatile("cp.async.wait_group 0;"); }
__device__ __forceinline__ void cp_wait1()  { asm volatile("cp.async.wait_group 1;"); }

__device__ __forceinline__ void mma_f16(float c[4], unsigned a0, unsigned a1,
                                        unsigned a2, unsigned a3,
                                        unsigned b0, unsigned b1) {
    asm volatile(
        "mma.sync.aligned.m16n8k16.row.col.f32.f16.f16.f32 "
        "{%0,%1,%2,%3}, {%4,%5,%6,%7}, {%8,%9}, {%0,%1,%2,%3};"
        : "+f"(c[0]), "+f"(c[1]), "+f"(c[2]), "+f"(c[3])
        : "r"(a0), "r"(a1), "r"(a2), "r"(a3), "r"(b0), "r"(b1));
}

__device__ __forceinline__ unsigned packh2(float lo, float hi) {
    __half2 h = __floats2half2_rn(lo, hi);
    return *(unsigned*)&h;
}

__device__ __forceinline__ unsigned ldu32(const __half* p) {
    return *(const unsigned*)p;
}

// ---------------------------------------------------------------------------
// fp32 -> fp16 elementwise (rn). n4 = n/4 float4 chunks.
// ---------------------------------------------------------------------------
__global__ void cvt_h(const float4* __restrict__ s, __half2* __restrict__ d, int n4)
{
    int i = blockIdx.x * blockDim.x + threadIdx.x;
    if (i >= n4) return;
    float4 v = s[i];
    d[2 * i]     = __floats2half2_rn(v.x, v.y);
    d[2 * i + 1] = __floats2half2_rn(v.z, v.w);
}

// ---------------------------------------------------------------------------
// Transpose + fp16 round: W[K][N] fp32 -> Wt[N][K] fp16
// ---------------------------------------------------------------------------
__global__ void cvt_t_h(const float* __restrict__ W, __half* __restrict__ Wt, int K, int N)
{
    __shared__ float t[32][33];
    int n0 = blockIdx.x << 5, k0 = blockIdx.y << 5;
    int tx = threadIdx.x, ty = threadIdx.y;
#pragma unroll
    for (int i = ty; i < 32; i += 8)
        t[i][tx] = W[(size_t)(k0 + i) * N + n0 + tx];
    __syncthreads();
#pragma unroll
    for (int i = ty; i < 32; i += 8)
        Wt[(size_t)(n0 + i) * K + k0 + tx] = __float2half(t[tx][i]);
}

// ---------------------------------------------------------------------------
// V -> V^T fp16: g_vth[(b*NH+h)*HD + d][t] = qkv_h[b][t][2048 + h*64 + d]
// ---------------------------------------------------------------------------
__global__ void vt_convert(const __half* __restrict__ qkv, __half* __restrict__ vt)
{
    __shared__ __half tile[32][34];
    int bh = blockIdx.z;
    int d0 = blockIdx.y << 5;
    int t0 = blockIdx.x << 5;
    int b = bh >> 4, h = bh & 15;
    int tx = threadIdx.x, ty = threadIdx.y;
#pragma unroll
    for (int i = ty; i < 32; i += 8)
        tile[i][tx] = qkv[((size_t)(b * T_SEQ + t0 + i)) * 3072 + 2048 + (h << 6) + d0 + tx];
    __syncthreads();
#pragma unroll
    for (int i = ty; i < 32; i += 8)
        vt[((size_t)bh * HD + d0 + i) * T_SEQ + t0 + tx] = tile[tx][i];
}

// ---------------------------------------------------------------------------
// Prep: per-head span/period/ratio, 1-D mask table over rel, span_loss scalar.
// ---------------------------------------------------------------------------
__global__ void prep_kernel(const float* __restrict__ span_p,
                            const float* __restrict__ period_w,
                            const float* __restrict__ ratio_w,
                            float* loss_out)
{
    __shared__ float s_span[NH], s_period[NH], s_ratio[NH];
    int tid = threadIdx.x;
    if (tid < NH) {
        float span   = 2048.f * sigmoidf_(span_p[tid]);
        float period = 2.f + 2.f * sigmoidf_(period_w[tid]);
        float ratio  = -0.25f + 0.5f * sigmoidf_(ratio_w[tid]);
        s_span[tid] = span; s_period[tid] = period; s_ratio[tid] = ratio;
        int cut = (int)floorf(32.f + span) + 1;
        if (cut > T_SEQ) cut = T_SEQ;
        g_cutoff[tid] = cut;
    }
    __syncthreads();
    for (int idx = tid; idx < NH * T_SEQ; idx += blockDim.x) {
        int hh = idx >> 11, rel = idx & (T_SEQ - 1);
        float span = s_span[hh], period = s_period[hh], ratio = s_ratio[hh];
        float mp = (32.f - (float)rel + span) * (1.f / 32.f);
        mp = fminf(fmaxf(mp, 0.f), 1.f);
        float amp = period * 0.25f;
        float wave = 0.5f * (cosf(6.28318530717958647692f * (float)rel / period) + 1.f) * amp
                     + 0.5f + period * ratio;
        wave = fminf(fmaxf(wave, 0.f), 1.f);
        g_mask[idx] = mp * wave;
    }
    if (tid == 0 && loss_out) {
        float s = 0.f;
        for (int h = 0; h < NH; h++) {
            float lt = 1.f / s_period[h] + 2.f * s_ratio[h] - 0.25f + 0.5f;
            s += (s_span[h] + 32.f) * lt;
        }
        *loss_out = 2e-6f * s * (1.f / 16.f);
    }
}

// ---------------------------------------------------------------------------
// FP16 tensor-core GEMM: C[M,N] = A[M,K] @ Bt[N,K]^T + bias[N]
// A, Bt fp16 K-major. CTA 128x256, 8 warps (2x4), warp 64x64, BK=32 halves,
// m16n8k16 mma, fp32 accum, 3-stage cp.async. M%128==0, N%256==0, K%32==0.
// OUT_HALF: store __half (else fp32).
// ---------------------------------------------------------------------------
#define GPADH 40                       /* halves per smem row (32 data + 8 pad) */
#define GA_STAGE_B (128 * GPADH * 2)   /* 10240 B */
#define GB_STAGE_B (256 * GPADH * 2)   /* 20480 B */
#define G_STAGE (GA_STAGE_B + GB_STAGE_B)
#define G_SMEM (3 * G_STAGE)           /* 92160 B */

template<int OUT_HALF>
__global__ __launch_bounds__(256, 1)
void gemm_h(const __half* __restrict__ A, const __half* __restrict__ Bt,
            const float* __restrict__ bias, void* __restrict__ Cout,
            int M, int N, int K)
{
    extern __shared__ char sg[];

    int tid  = threadIdx.x;
    int wid  = tid >> 5, lane = tid & 31;
    int gro  = lane >> 2, tig = lane & 3;
    int wm   = (wid >> 2) << 6;   // 0/64
    int wn   = (wid & 3) << 6;    // 0/64/128/192
    int bm   = blockIdx.y << 7;
    int bn   = blockIdx.x << 8;

    float acc[4][8][4];
#pragma unroll
    for (int mt = 0; mt < 4; mt++)
#pragma unroll
        for (int nt = 0; nt < 8; nt++)
#pragma unroll
            for (int e = 0; e < 4; e++) acc[mt][nt][e] = 0.f;

    int nk = K >> 5;   // 32-half k-blocks

    auto load_stage = [&](int s, int kb) {
        const __half* Ag = A + (size_t)bm * K + kb * 32;
        const __half* Bg = Bt + (size_t)bn * K + kb * 32;
        char* as = sg + s * G_STAGE;
        char* bs = as + GA_STAGE_B;
#pragma unroll
        for (int it = 0; it < 2; it++) {           // A: 512 x 16B chunks
            int id = tid + (it << 8);
            int row = id >> 2, c = id & 3;
            cp16(as + row * (GPADH * 2) + c * 16, Ag + (size_t)row * K + c * 8);
        }
#pragma unroll
        for (int it = 0; it < 4; it++) {           // B: 1024 x 16B chunks
            int id = tid + (it << 8);
            int row = id >> 2, c = id & 3;
            cp16(bs + row * (GPADH * 2) + c * 16, Bg + (size_t)row * K + c * 8);
        }
        cp_commit();
    };

    load_stage(0, 0);
    load_stage(1, 1);

    int sc = 0, sl = 2;
    for (int kb = 0; kb < nk; kb++) {
        cp_wait1();
        __syncthreads();
        if (kb + 2 < nk) load_stage(sl, kb + 2);
        else cp_commit();   // keep group count in lockstep for wait_group 1

        const __half* as = (const __half*)(sg + sc * G_STAGE);
        const __half* bs = (const __half*)(sg + sc * G_STAGE + GA_STAGE_B);
#pragma unroll
        for (int ks = 0; ks < 2; ks++) {           // two k16 steps per block
            int kof = (ks << 4) + (tig << 1);
            unsigned af[4][4];
#pragma unroll
            for (int mt = 0; mt < 4; mt++) {
                int rb = wm + (mt << 4) + gro;
                af[mt][0] = ldu32(as + rb * GPADH + kof);
                af[mt][1] = ldu32(as + (rb + 8) * GPADH + kof);
                af[mt][2] = ldu32(as + rb * GPADH + kof + 8);
                af[mt][3] = ldu32(as + (rb + 8) * GPADH + kof + 8);
            }
            unsigned bf[8][2];
#pragma unroll
            for (int nt = 0; nt < 8; nt++) {
                int nb = wn + (nt << 3) + gro;
                bf[nt][0] = ldu32(bs + nb * GPADH + kof);
                bf[nt][1] = ldu32(bs + nb * GPADH + kof + 8);
            }
#pragma unroll
            for (int mt = 0; mt < 4; mt++)
#pragma unroll
                for (int nt = 0; nt < 8; nt++)
                    mma_f16(acc[mt][nt], af[mt][0], af[mt][1], af[mt][2], af[mt][3],
                            bf[nt][0], bf[nt][1]);
        }
        sc = (sc == 2) ? 0 : sc + 1;
        sl = (sl == 2) ? 0 : sl + 1;
    }

#pragma unroll
    for (int mt = 0; mt < 4; mt++) {
        int row = bm + wm + (mt << 4) + gro;
#pragma unroll
        for (int nt = 0; nt < 8; nt++) {
            int col = bn + wn + (nt << 3) + (tig << 1);
            float2 bz = *(const float2*)(bias + col);
            float o00 = acc[mt][nt][0] + bz.x, o01 = acc[mt][nt][1] + bz.y;
            float o10 = acc[mt][nt][2] + bz.x, o11 = acc[mt][nt][3] + bz.y;
            if (OUT_HALF) {
                __half* C = (__half*)Cout;
                *(unsigned*)(C + (size_t)row * N + col)       = packh2(o00, o01);
                *(unsigned*)(C + (size_t)(row + 8) * N + col) = packh2(o10, o11);
            } else {
                float* C = (float*)Cout;
                *(float2*)(C + (size_t)row * N + col)       = make_float2(o00, o01);
                *(float2*)(C + (size_t)(row + 8) * N + col) = make_float2(o10, o11);
            }
        }
    }
}

// ---------------------------------------------------------------------------
// Banded flash attention: fp16 QK^T (m16n8k16) + fp32 softmax + fp16 PV.
// CTA = (b, h, 128 query rows), 8 warps. K and V^T staged fp16, double-buffered.
// ---------------------------------------------------------------------------
#define KPADH 72                     /* halves per K smem row (64 + 8 pad) */
#define KS_B (64 * KPADH * 2)        /* 9216 B per K buffer */
#define VS_B (64 * KPADH * 2)        /* 9216 B per V buffer */
#define ATTN_SMEM (2 * KS_B + 2 * VS_B)

__global__ __launch_bounds__(256)
void attn_h(const __half* __restrict__ qkv, const __half* __restrict__ vth,
            __half* __restrict__ yout)
{
    extern __shared__ char smc[];
    __half* Kb0 = (__half*)smc;
    __half* Kb1 = (__half*)(smc + KS_B);
    __half* V0  = (__half*)(smc + 2 * KS_B);
    __half* V1  = (__half*)(smc + 2 * KS_B + VS_B);

    int tid  = threadIdx.x;
    int wid  = tid >> 5, lane = tid & 31;
    int gro  = lane >> 2, tig = lane & 3;
    int i0   = blockIdx.x << 7;
    int h    = blockIdx.y, b = blockIdx.z;
    int baseq = h << 6;
    int wrow = wid << 4;
    int ir0 = i0 + wrow + gro;
    int ir1 = ir0 + 8;

    // ---- Q fragments (fp16, once per block) ----
    const __half* qp = qkv + ((size_t)(b * T_SEQ + i0 + wrow)) * 3072 + baseq;
    unsigned qf[4][4];
#pragma unroll
    for (int kt = 0; kt < 4; kt++) {
        int kc = (kt << 4) + (tig << 1);
        qf[kt][0] = ldu32(qp + gro * 3072 + kc);
        qf[kt][1] = ldu32(qp + (gro + 8) * 3072 + kc);
        qf[kt][2] = ldu32(qp + gro * 3072 + kc + 8);
        qf[kt][3] = ldu32(qp + (gro + 8) * 3072 + kc + 8);
    }

    float m0 = -1e30f, m1 = -1e30f, l0 = 0.f, l1 = 0.f;
    float oreg[8][4];
#pragma unroll
    for (int nt = 0; nt < 8; nt++)
#pragma unroll
        for (int e = 0; e < 4; e++) oreg[nt][e] = 0.f;

    int cutoff = g_cutoff[h];
    int t0 = i0 - cutoff + 1;
    int jstart = (t0 <= 0) ? 0 : (t0 & ~63);
    int jend = i0 + 64;
    const float* maskh = g_mask + h * T_SEQ;
    const __half* vbase = vth + ((size_t)(b * NH + h)) * HD * T_SEQ;

    auto stage_tile = [&](__half* Kn, __half* Vn, int j0) {
        const __half* kb = qkv + ((size_t)(b * T_SEQ + j0)) * 3072 + baseq + 1024;
#pragma unroll
        for (int it = 0; it < 2; it++) {       // K: 512 x 16B chunks
            int id = tid + (it << 8);
            int row = id >> 3, c = id & 7;
            cp16(Kn + row * KPADH + c * 8, kb + (size_t)row * 3072 + c * 8);
        }
#pragma unroll
        for (int it = 0; it < 2; it++) {       // V^T: 512 x 16B chunks
            int id = tid + (it << 8);
            int row = id >> 3, c = id & 7;
            cp16(Vn + row * KPADH + c * 8, vbase + (size_t)row * T_SEQ + j0 + c * 8);
        }
        cp_commit();
    };

    stage_tile(Kb0, V0, jstart);

    int buf = 0;
    for (int j0 = jstart; j0 <= jend; j0 += 64) {
        cp_wait0();
        __syncthreads();
        if (j0 + 64 <= jend)
            stage_tile(buf ? Kb0 : Kb1, buf ? V0 : V1, j0 + 64);
        const __half* Kc = buf ? Kb1 : Kb0;
        const __half* Vc = buf ? V1  : V0;

        // ---- S = Q K^T (16x64 per warp, fp16 k16) ----
        float sreg[8][4];
#pragma unroll
        for (int nt = 0; nt < 8; nt++) {
#pragma unroll
            for (int e = 0; e < 4; e++) sreg[nt][e] = 0.f;
            int jb = (nt << 3) + gro;
#pragma unroll
            for (int kt = 0; kt < 4; kt++) {
                int kof = (kt << 4) + (tig << 1);
                unsigned b0 = ldu32(Kc + jb * KPADH + kof);
                unsigned b1 = ldu32(Kc + jb * KPADH + kof + 8);
                mma_f16(sreg[nt], qf[kt][0], qf[kt][1], qf[kt][2], qf[kt][3], b0, b1);
            }
        }

        // ---- online softmax (fp32) ----
        float vm0 = -1e30f, vm1 = -1e30f;
#pragma unroll
        for (int nt = 0; nt < 8; nt++) {
            int jn = j0 + (nt << 3) + (tig << 1);
            float s0 = (jn     <= ir0) ? sreg[nt][0] * 0.125f : -1e30f;
            float s1 = (jn + 1 <= ir0) ? sreg[nt][1] * 0.125f : -1e30f;
            float s2 = (jn     <= ir1) ? sreg[nt][2] * 0.125f : -1e30f;
            float s3 = (jn + 1 <= ir1) ? sreg[nt][3] * 0.125f : -1e30f;
            sreg[nt][0] = s0; sreg[nt][1] = s1; sreg[nt][2] = s2; sreg[nt][3] = s3;
            vm0 = fmaxf(vm0, fmaxf(s0, s1));
            vm1 = fmaxf(vm1, fmaxf(s2, s3));
        }
        vm0 = fmaxf(vm0, __shfl_xor_sync(0xffffffffu, vm0, 1));
        vm0 = fmaxf(vm0, __shfl_xor_sync(0xffffffffu, vm0, 2));
        vm1 = fmaxf(vm1, __shfl_xor_sync(0xffffffffu, vm1, 1));
        vm1 = fmaxf(vm1, __shfl_xor_sync(0xffffffffu, vm1, 2));
        float mn0 = fmaxf(m0, vm0), mn1 = fmaxf(m1, vm1);
        float f0 = __expf(m0 - mn0), f1 = __expf(m1 - mn1);
        float rs0 = 0.f, rs1 = 0.f;
#pragma unroll
        for (int nt = 0; nt < 8; nt++) {
            int jn = j0 + (nt << 3) + (tig << 1);
            float p0 = 0.f, p1 = 0.f, p2 = 0.f, p3 = 0.f;
            if (jn <= ir0) {
                int r = ir0 - jn; if (r > 2047) r = 2047;
                p0 = __expf(sreg[nt][0] - mn0) * __ldg(maskh + r);
            }
            if (jn + 1 <= ir0) {
                int r = ir0 - jn - 1; if (r > 2047) r = 2047;
                p1 = __expf(sreg[nt][1] - mn0) * __ldg(maskh + r);
            }
            if (jn <= ir1) {
                int r = ir1 - jn; if (r > 2047) r = 2047;
                p2 = __expf(sreg[nt][2] - mn1) * __ldg(maskh + r);
            }
            if (jn + 1 <= ir1) {
                int r = ir1 - jn - 1; if (r > 2047) r = 2047;
                p3 = __expf(sreg[nt][3] - mn1) * __ldg(maskh + r);
            }
            sreg[nt][0] = p0; sreg[nt][1] = p1; sreg[nt][2] = p2; sreg[nt][3] = p3;
            rs0 += p0 + p1; rs1 += p2 + p3;
        }
        rs0 += __shfl_xor_sync(0xffffffffu, rs0, 1);
        rs0 += __shfl_xor_sync(0xffffffffu, rs0, 2);
        rs1 += __shfl_xor_sync(0xffffffffu, rs1, 1);
        rs1 += __shfl_xor_sync(0xffffffffu, rs1, 2);
        l0 = l0 * f0 + rs0; m0 = mn0;
        l1 = l1 * f1 + rs1; m1 = mn1;
#pragma unroll
        for (int nt = 0; nt < 8; nt++) {
            oreg[nt][0] *= f0; oreg[nt][1] *= f0;
            oreg[nt][2] *= f1; oreg[nt][3] *= f1;
        }

        // ---- O += P V : fp16 m16n8k16, P packed straight from C-layout ----
#pragma unroll
        for (int kt = 0; kt < 4; kt++) {
            unsigned a0 = packh2(sreg[2 * kt][0],     sreg[2 * kt][1]);
            unsigned a1 = packh2(sreg[2 * kt][2],     sreg[2 * kt][3]);
            unsigned a2 = packh2(sreg[2 * kt + 1][0], sreg[2 * kt + 1][1]);
            unsigned a3 = packh2(sreg[2 * kt + 1][2], sreg[2 * kt + 1][3]);
            int kb = (kt << 4) + (tig << 1);
#pragma unroll
            for (int nt = 0; nt < 8; nt++) {
                int nb = (nt << 3) + gro;
                unsigned b0 = ldu32(Vc + nb * KPADH + kb);
                unsigned b1 = ldu32(Vc + nb * KPADH + kb + 8);
                mma_f16(oreg[nt], a0, a1, a2, a3, b0, b1);
            }
        }
        buf ^= 1;
    }

    // ---- epilogue (fp16: feeds GEMM2) ----
    float inv0 = 1.f / l0, inv1 = 1.f / l1;
#pragma unroll
    for (int nt = 0; nt < 8; nt++) {
        int col = baseq + (nt << 3) + (tig << 1);
        unsigned o0 = packh2(oreg[nt][0] * inv0, oreg[nt][1] * inv0);
        unsigned o1 = packh2(oreg[nt][2] * inv1, oreg[nt][3] * inv1);
        *(unsigned*)(yout + ((size_t)(b * T_SEQ + ir0)) * 1024 + col) = o0;
        *(unsigned*)(yout + ((size_t)(b * T_SEQ + ir1)) * 1024 + col) = o1;
    }
}

// ---------------------------------------------------------------------------
extern "C" void kernel_launch(void* const* d_in, const int* in_sizes, int n_in,
                              void* d_out, int out_size)
{
    const float* x        = (const float*)d_in[0];
    const float* w_attn   = (const float*)d_in[1];
    const float* b_attn   = (const float*)d_in[2];
    const float* w_proj   = (const float*)d_in[3];
    const float* b_proj   = (const float*)d_in[4];
    const float* span_p   = (const float*)d_in[5];
    const float* period_w = (const float*)d_in[6];
    const float* ratio_w  = (const float*)d_in[7];
    float* out = (float*)d_out;

    void* p;
    cudaGetSymbolAddress(&p, g_qkv);  __half* qkv  = (__half*)p;
    cudaGetSymbolAddress(&p, g_attn); __half* attn = (__half*)p;
    cudaGetSymbolAddress(&p, g_xh);   __half* xh   = (__half*)p;
    cudaGetSymbolAddress(&p, g_wah);  __half* wah  = (__half*)p;
    cudaGetSymbolAddress(&p, g_wph);  __half* wph  = (__half*)p;
    cudaGetSymbolAddress(&p, g_vth);  __half* vth  = (__half*)p;

    cudaFuncSetAttribute(gemm_h<1>, cudaFuncAttributeMaxDynamicSharedMemorySize, G_SMEM);
    cudaFuncSetAttribute(gemm_h<0>, cudaFuncAttributeMaxDynamicSharedMemorySize, G_SMEM);
    cudaFuncSetAttribute(attn_h, cudaFuncAttributeMaxDynamicSharedMemorySize, ATTN_SMEM);

    float* loss_ptr = (out_size > MTOT * C_EMB) ? out + MTOT * C_EMB : nullptr;

    prep_kernel<<<1, 256>>>(span_p, period_w, ratio_w, loss_ptr);
    cvt_h<<<(MTOT * C_EMB / 4) / 256, 256>>>((const float4*)x, (__half2*)xh,
                                             MTOT * C_EMB / 4);
    cvt_t_h<<<dim3(3 * C_EMB / 32, C_EMB / 32), dim3(32, 8)>>>(w_attn, wah, C_EMB, 3 * C_EMB);
    cvt_t_h<<<dim3(C_EMB / 32, C_EMB / 32), dim3(32, 8)>>>(w_proj, wph, C_EMB, C_EMB);

    gemm_h<1><<<dim3(3 * C_EMB / 256, MTOT / 128), 256, G_SMEM>>>(
        xh, wah, b_attn, qkv, MTOT, 3 * C_EMB, C_EMB);
    vt_convert<<<dim3(T_SEQ / 32, HD / 32, 2 * NH), dim3(32, 8)>>>(qkv, vth);
    attn_h<<<dim3(T_SEQ / 128, NH, 2), 256, ATTN_SMEM>>>(qkv, vth, attn);
    gemm_h<0><<<dim3(C_EMB / 256, MTOT / 128), 256, G_SMEM>>>(
        attn, wph, b_proj, out, MTOT, C_EMB, C_EMB);
}